// round 9
// baseline (speedup 1.0000x reference)
#include <cuda_runtime.h>
#include <cuda_bf16.h>
#include <cstdint>

// ---------------- problem constants ----------------
#define TWO_N   16384
#define NHALF   8192
#define DK      256
#define BAND    64            // 64-row bands, 64-col tiles
#define NBANDS  256
#define SAPAD   264           // padded smem row stride in bf16 (528B)
#define TILE_BYTES2 (BAND * SAPAD * 2)   // 33792 B

// tile-list scheduling: 32896 upper-tri 64x64 tiles over 296 CTAs
#define NCTA    296
#define BIGCHUNK 112
#define NBIG    40            // 40*112 + 256*111 = 32896
#define BIGLIN  (NBIG * BIGCHUNK)   // 4480
#define NSLOT   6

#define NTHREADS 256

// smem: scratch (2KB) | A tile | B tile x2  => 103424 B (2 CTAs/SM)
#define SM_A       2048
#define SM_B       (SM_A + TILE_BYTES2)
#define SMEM_BYTES (SM_B + 2 * TILE_BYTES2)

// ---------------- device scratch ----------------
__device__ __align__(16) __nv_bfloat16 g_zn[TWO_N * DK];
__device__ float g_rnorm[TWO_N];
__device__ float g_pos[NHALF];
__device__ float g_rowsum[TWO_N];
__device__ float g_partA[64];
__device__ float g_partB[64];
// column-sum contributions: [band(writer)*2 + wm][col]  (single writer per tile strip)
__device__ float g_cs[NBANDS * 2 * TWO_N];
// row partials: [band][slot][64]  (zeroed each run; single writer per slot)
__device__ float g_bandparts[NBANDS * NSLOT * BAND];

#define SCALE_L2E 14.426950408889634f   // 10 * log2(e)

// ---------------- helpers ----------------
__device__ __forceinline__ float fast_ex2(float x) {
    float y;
    asm("ex2.approx.f32 %0, %1;" : "=f"(y) : "f"(x));
    return y;
}
__device__ __forceinline__ uint32_t smem_u32(const void* p) {
    uint32_t a;
    asm("{ .reg .u64 t; cvta.to.shared.u64 t, %1; cvt.u32.u64 %0, t; }" : "=r"(a) : "l"(p));
    return a;
}
__device__ __forceinline__ void cp16(uint32_t dst, const void* src) {
    asm volatile("cp.async.cg.shared.global [%0], [%1], 16;\n" :: "r"(dst), "l"(src));
}
__device__ __forceinline__ void cp_commit() { asm volatile("cp.async.commit_group;\n"); }
__device__ __forceinline__ void cp_wait0()  { asm volatile("cp.async.wait_group 0;\n"); }

__device__ __forceinline__ void ldsm4(uint32_t* r, uint32_t addr) {
    asm volatile("ldmatrix.sync.aligned.m8n8.x4.shared.b16 {%0,%1,%2,%3}, [%4];"
                 : "=r"(r[0]), "=r"(r[1]), "=r"(r[2]), "=r"(r[3]) : "r"(addr));
}
__device__ __forceinline__ void mma16816(float* c, const uint32_t* a, uint32_t b0, uint32_t b1) {
    asm volatile(
        "mma.sync.aligned.m16n8k16.row.col.f32.bf16.bf16.f32 "
        "{%0,%1,%2,%3}, {%4,%5,%6,%7}, {%8,%9}, {%0,%1,%2,%3};\n"
        : "+f"(c[0]), "+f"(c[1]), "+f"(c[2]), "+f"(c[3])
        : "r"(a[0]), "r"(a[1]), "r"(a[2]), "r"(a[3]), "r"(b0), "r"(b1));
}
__device__ __forceinline__ int chunk_owner(int L) {
    return (L < BIGLIN) ? (L / BIGCHUNK) : NBIG + (L - BIGLIN) / (BIGCHUNK - 1);
}

// ---------------- kernel 1: row-normalize -> bf16 ----------------
__global__ void normalize_kernel(const float* __restrict__ z1, const float* __restrict__ z2) {
    int warp = threadIdx.x >> 5, lane = threadIdx.x & 31;
    int row = blockIdx.x * 8 + warp;
    const float* src = (row < NHALF) ? (z1 + (size_t)row * DK)
                                     : (z2 + (size_t)(row - NHALF) * DK);
    float4 v0 = ((const float4*)src)[lane];
    float4 v1 = ((const float4*)src)[lane + 32];
    float ss = v0.x*v0.x + v0.y*v0.y + v0.z*v0.z + v0.w*v0.w
             + v1.x*v1.x + v1.y*v1.y + v1.z*v1.z + v1.w*v1.w;
    #pragma unroll
    for (int o = 16; o > 0; o >>= 1) ss += __shfl_xor_sync(0xffffffffu, ss, o);
    float rn = 1.0f / fmaxf(sqrtf(ss), 1e-6f);
    if (lane == 0) g_rnorm[row] = rn;

    __nv_bfloat162 w0a = __floats2bfloat162_rn(v0.x * rn, v0.y * rn);
    __nv_bfloat162 w0b = __floats2bfloat162_rn(v0.z * rn, v0.w * rn);
    __nv_bfloat162 w1a = __floats2bfloat162_rn(v1.x * rn, v1.y * rn);
    __nv_bfloat162 w1b = __floats2bfloat162_rn(v1.z * rn, v1.w * rn);
    uint2 p0, p1;
    memcpy(&p0.x, &w0a, 4); memcpy(&p0.y, &w0b, 4);
    memcpy(&p1.x, &w1a, 4); memcpy(&p1.y, &w1b, 4);
    uint2* dst = (uint2*)(g_zn + (size_t)row * DK);
    dst[lane]      = p0;
    dst[lane + 32] = p1;
}

// ---------------- kernel 2: fp32 positives ----------------
__global__ void pos_kernel(const float* __restrict__ z1, const float* __restrict__ z2) {
    int warp = threadIdx.x >> 5, lane = threadIdx.x & 31;
    int i = blockIdx.x * 8 + warp;
    const float* a = z1 + (size_t)i * DK;
    const float* b = z2 + (size_t)i * DK;
    float4 a0 = ((const float4*)a)[lane];
    float4 a1 = ((const float4*)a)[lane + 32];
    float4 b0 = ((const float4*)b)[lane];
    float4 b1 = ((const float4*)b)[lane + 32];
    float d = a0.x*b0.x + a0.y*b0.y + a0.z*b0.z + a0.w*b0.w
            + a1.x*b1.x + a1.y*b1.y + a1.z*b1.z + a1.w*b1.w;
    #pragma unroll
    for (int o = 16; o > 0; o >>= 1) d += __shfl_xor_sync(0xffffffffu, d, o);
    if (lane == 0) {
        float p = d * g_rnorm[i] * g_rnorm[i + NHALF];
        p = fminf(fmaxf(p, -1.0f + 1e-6f), 1.0f - 1e-6f);
        g_pos[i] = p;
    }
}

// ---------------- kernel 2b: zero g_bandparts ----------------
__global__ void zero_bp_kernel() {
    int i = blockIdx.x * 256 + threadIdx.x;    // 96 blocks * 256 * 4 = 98304 floats
    ((float4*)g_bandparts)[i] = make_float4(0.f, 0.f, 0.f, 0.f);
}

// ---------------- kernel 3: symmetric HMMA sim-GEMM, 64x64 tiles, 2 CTAs/SM ----------------
// warps: wm = w>>2 (rows wm*32..+32), wn = w&3 (cols wn*16..+16)
__global__ __launch_bounds__(NTHREADS, 2) void simloss_occ2() {
    extern __shared__ char smem_raw[];
    const uint32_t sbase = smem_u32(smem_raw);
    const uint32_t sA  = sbase + SM_A;
    const uint32_t sB0 = sbase + SM_B;

    const int tid  = threadIdx.x;
    const int lane = tid & 31;
    const int w    = tid >> 5;
    const int wm   = w >> 2;       // 0..1
    const int wn   = w & 3;        // 0..3
    const int g    = lane >> 2;
    const int tg   = lane & 3;

    const int cta = blockIdx.x;
    const int s_lin = (cta < NBIG) ? cta * BIGCHUNK : BIGLIN + (cta - NBIG) * (BIGCHUNK - 1);
    const int e_lin = s_lin + ((cta < NBIG) ? BIGCHUNK : (BIGCHUNK - 1));

    // ldmatrix per-lane offsets
    const int lrow = lane & 15;
    const int lchk = lane >> 4;
    const uint32_t aOff  = (uint32_t)(((wm * 32 + lrow) * SAPAD + lchk * 8) * 2);
    const uint32_t aOff2 = aOff + (uint32_t)(16 * SAPAD * 2);
    const uint32_t bOff  = (uint32_t)(((wn * 16 + lrow) * SAPAD + lchk * 8) * 2);

    float* sred = (float*)smem_raw;   // 256 floats scratch

    int idx = s_lin;
    while (idx < e_lin) {
        // ---- map linear idx -> (band, tile t0) via snake order ----
        // j even -> band j/2 (size 256-j/2); j odd -> band 255-j/2 (size 1+j/2)
        int cum = 0, band = 0;
        #pragma unroll 1
        for (int j = 0; j < 256; ++j) {
            int bb = (j & 1) ? (255 - (j >> 1)) : (j >> 1);
            int sz = NBANDS - bb;
            if (idx < cum + sz) { band = bb; break; }
            cum += sz;
        }
        const int t0 = band + (idx - cum);
        int t1 = t0 + (e_lin - idx) - 1;
        if (t1 > NBANDS - 1) t1 = NBANDS - 1;
        const int nb = t1 - t0 + 1;
        const int slot = cta - chunk_owner(cum);

        // ---- load A(band) + B(t0) ----
        {
            const __nv_bfloat16* gA = g_zn + (size_t)band * BAND * DK;
            const __nv_bfloat16* gB = g_zn + (size_t)t0 * BAND * DK;
            #pragma unroll
            for (int k = 0; k < 8; ++k) {
                int id = tid + k * NTHREADS;
                int r = id >> 5, ccx = id & 31;
                uint32_t so = (uint32_t)((r * SAPAD + ccx * 8) * 2);
                cp16(sA + so, gA + (size_t)r * DK + ccx * 8);
                cp16(sB0 + so, gB + (size_t)r * DK + ccx * 8);
            }
            cp_commit(); cp_wait0();
        }
        __syncthreads();

        float racc[4] = {0.f, 0.f, 0.f, 0.f};

        for (int i2 = 0; i2 < nb; ++i2) {
            const int t = t0 + i2;
            const uint32_t sBc = sB0 + (uint32_t)((i2 & 1) * TILE_BYTES2);

            if (i2 + 1 < nb) {
                const uint32_t sBn = sB0 + (uint32_t)(((i2 + 1) & 1) * TILE_BYTES2);
                const __nv_bfloat16* gB = g_zn + (size_t)(t + 1) * BAND * DK;
                #pragma unroll
                for (int k = 0; k < 8; ++k) {
                    int id = tid + k * NTHREADS;
                    int r = id >> 5, ccx = id & 31;
                    cp16(sBn + (uint32_t)((r * SAPAD + ccx * 8) * 2), gB + (size_t)r * DK + ccx * 8);
                }
            }
            cp_commit();

            float acc[2][2][4];
            #pragma unroll
            for (int mf = 0; mf < 2; ++mf)
                #pragma unroll
                for (int nf = 0; nf < 2; ++nf)
                    #pragma unroll
                    for (int q = 0; q < 4; ++q) acc[mf][nf][q] = 0.f;

            #pragma unroll
            for (int ks = 0; ks < 16; ++ks) {
                const uint32_t kb = (uint32_t)(ks * 32);
                uint32_t a0[4], a1[4], bA[4];
                ldsm4(a0, sA + aOff + kb);
                ldsm4(a1, sA + aOff2 + kb);
                ldsm4(bA, sBc + bOff + kb);

                mma16816(acc[0][0], a0, bA[0], bA[2]);
                mma16816(acc[1][0], a1, bA[0], bA[2]);
                mma16816(acc[0][1], a0, bA[1], bA[3]);
                mma16816(acc[1][1], a1, bA[1], bA[3]);
            }

            // ---- epilogue: exp, mask (diag tile: c<=r -> 0), row + column sums ----
            const bool diag = (t == band);
            float cc4[4];
            #pragma unroll
            for (int j = 0; j < 4; ++j) cc4[j] = 0.f;

            #pragma unroll
            for (int mf = 0; mf < 2; ++mf)
                #pragma unroll
                for (int nf = 0; nf < 2; ++nf)
                    #pragma unroll
                    for (int q = 0; q < 4; ++q) {
                        float e = fast_ex2(acc[mf][nf][q] * SCALE_L2E);
                        if (diag) {
                            int rl = wm * 32 + mf * 16 + (q >> 1) * 8 + g;
                            int cl = wn * 16 + nf * 8 + tg * 2 + (q & 1);
                            if (cl <= rl) e = 0.f;
                        }
                        racc[mf * 2 + (q >> 1)] += e;
                        cc4[nf * 2 + (q & 1)] += e;
                    }

            // column sums: reduce over g lanes, store (always — diag too)
            #pragma unroll
            for (int j = 0; j < 4; ++j) {
                cc4[j] += __shfl_xor_sync(0xffffffffu, cc4[j], 4);
                cc4[j] += __shfl_xor_sync(0xffffffffu, cc4[j], 8);
                cc4[j] += __shfl_xor_sync(0xffffffffu, cc4[j], 16);
            }
            if (g == 0) {
                float* dst = g_cs + (size_t)(band * 2 + wm) * TWO_N
                           + t * BAND + wn * 16 + tg * 2;
                #pragma unroll
                for (int j = 0; j < 4; ++j) dst[(j >> 1) * 8 + (j & 1)] = cc4[j];
            }

            cp_wait0();
            __syncthreads();
        }

        // ---- flush row partials for this band segment ----
        #pragma unroll
        for (int k2 = 0; k2 < 4; ++k2) {
            racc[k2] += __shfl_xor_sync(0xffffffffu, racc[k2], 1);
            racc[k2] += __shfl_xor_sync(0xffffffffu, racc[k2], 2);
        }
        if (tg == 0) {
            #pragma unroll
            for (int mf = 0; mf < 2; ++mf)
                #pragma unroll
                for (int h = 0; h < 2; ++h)
                    sred[wn * 64 + wm * 32 + mf * 16 + h * 8 + g] = racc[mf * 2 + h];
        }
        __syncthreads();
        if (tid < 64) {
            g_bandparts[(band * NSLOT + slot) * BAND + tid] =
                sred[tid] + sred[64 + tid] + sred[128 + tid] + sred[192 + tid];
        }
        __syncthreads();

        idx += nb;
    }
}

// ---------------- kernel 3b: combine partials + transposed column sums, take log ----------------
// grid 256 x 256: band B = blockIdx.x (64 rows); 4 thread-chunks split the b' loop.
__global__ void rowfinal_kernel() {
    __shared__ float sm[256];
    const int B = blockIdx.x;
    const int rl = threadIdx.x & 63;
    const int chunk = threadIdx.x >> 6;
    const int r = B * BAND + rl;
    float sacc = 0.f;
    for (int b = chunk; b <= B; b += 4) {
        const float* p2 = g_cs + (size_t)(b * 2) * TWO_N + r;
        sacc += p2[0] + p2[TWO_N];
    }
    sm[threadIdx.x] = sacc;
    __syncthreads();
    if (chunk == 0) {
        float tot = sm[rl] + sm[rl + 64] + sm[rl + 128] + sm[rl + 192];
        const float* bp = g_bandparts + (size_t)B * NSLOT * BAND + rl;
        #pragma unroll
        for (int s = 0; s < NSLOT; ++s) tot += bp[s * BAND];
        g_rowsum[r] = logf(tot);
    }
}

// ---------------- kernel 4: two-stage final reduce ----------------
__global__ void reduce1_kernel() {
    __shared__ float sa[256], sb[256];
    int b = blockIdx.x, tid = threadIdx.x;
    float a = g_rowsum[b * 256 + tid];          // already log
    float pp = (tid < 128) ? g_pos[b * 128 + tid] : 0.f;
    sa[tid] = a; sb[tid] = pp;
    __syncthreads();
    for (int s = 128; s > 0; s >>= 1) {
        if (tid < s) { sa[tid] += sa[tid + s]; sb[tid] += sb[tid + s]; }
        __syncthreads();
    }
    if (tid == 0) { g_partA[b] = sa[0]; g_partB[b] = sb[0]; }
}

__global__ void reduce2_kernel(float* __restrict__ out) {
    __shared__ float sa[64], sb[64];
    int tid = threadIdx.x;
    sa[tid] = g_partA[tid]; sb[tid] = g_partB[tid];
    __syncthreads();
    for (int s = 32; s > 0; s >>= 1) {
        if (tid < s) { sa[tid] += sa[tid + s]; sb[tid] += sb[tid + s]; }
        __syncthreads();
    }
    if (tid == 0) out[0] = (sa[0] - 20.0f * sb[0]) / (float)TWO_N;
}

// ---------------- launch ----------------
extern "C" void kernel_launch(void* const* d_in, const int* in_sizes, int n_in,
                              void* d_out, int out_size) {
    const float* z1 = (const float*)d_in[0];
    const float* z2 = (const float*)d_in[1];
    float* out = (float*)d_out;

    normalize_kernel<<<2048, 256>>>(z1, z2);
    pos_kernel<<<1024, 256>>>(z1, z2);
    zero_bp_kernel<<<96, 256>>>();
    cudaFuncSetAttribute(simloss_occ2, cudaFuncAttributeMaxDynamicSharedMemorySize, SMEM_BYTES);
    simloss_occ2<<<NCTA, NTHREADS, SMEM_BYTES>>>();
    rowfinal_kernel<<<256, 256>>>();
    reduce1_kernel<<<64, 256>>>();
    reduce2_kernel<<<1, 64>>>(out);
}

// round 11
// speedup vs baseline: 1.1234x; 1.1234x over previous
#include <cuda_runtime.h>
#include <cuda_bf16.h>
#include <cstdint>

// ---------------- problem constants ----------------
#define TWO_N   16384
#define NHALF   8192
#define DK      256
#define MT      128
#define NT      128
#define SAPAD   264      // padded smem row stride in bf16 (528B; conflict-free ldmatrix)
#define TILE_BYTES2 (MT * SAPAD * 2)

// tile-list scheduling: 8256 upper-tri tiles over 148 CTAs
#define NCTA    148
#define BIGCHUNK 56
#define NBIG    116          // 116*56 + 32*55 = 8256
#define BIGLIN  (NBIG * BIGCHUNK)   // 6496
#define NSLOT   6

#define NTHREADS 256

// smem: scratch (2KB) | A tile | B tile x2
#define SM_A       2048
#define SM_B       (SM_A + TILE_BYTES2)
#define SMEM_BYTES (SM_B + 2 * TILE_BYTES2)   // 204800 B

#define SCALE_L2E 14.426950408889634f   // 10 * log2(e)

// ---------------- device scratch ----------------
__device__ __align__(16) __nv_bfloat16 g_zn[TWO_N * DK];
__device__ float g_rnorm[TWO_N];
__device__ float g_pos[NHALF];
__device__ float g_rowsum[TWO_N];
__device__ float g_partA[64];
__device__ float g_partB[64];
// column-sum contributions: [band(writer) * 2 + wm][col]  (single-writer per tile)
__device__ float g_cs[128 * 2 * TWO_N];
// row partials: [band][slot][row]  (zeroed each run; single writer per slot)
__device__ float g_bandparts[128 * NSLOT * 128];

// ---------------- helpers ----------------
__device__ __forceinline__ float fast_ex2(float x) {
    float y;
    asm("ex2.approx.f32 %0, %1;" : "=f"(y) : "f"(x));
    return y;
}
__device__ __forceinline__ uint32_t smem_u32(const void* p) {
    uint32_t a;
    asm("{ .reg .u64 t; cvta.to.shared.u64 t, %1; cvt.u32.u64 %0, t; }" : "=r"(a) : "l"(p));
    return a;
}
__device__ __forceinline__ void cp16(uint32_t dst, const void* src) {
    asm volatile("cp.async.cg.shared.global [%0], [%1], 16;\n" :: "r"(dst), "l"(src));
}
__device__ __forceinline__ void cp_commit() { asm volatile("cp.async.commit_group;\n"); }
__device__ __forceinline__ void cp_wait0()  { asm volatile("cp.async.wait_group 0;\n"); }

__device__ __forceinline__ void ldsm4(uint32_t* r, uint32_t addr) {
    asm volatile("ldmatrix.sync.aligned.m8n8.x4.shared.b16 {%0,%1,%2,%3}, [%4];"
                 : "=r"(r[0]), "=r"(r[1]), "=r"(r[2]), "=r"(r[3]) : "r"(addr));
}
__device__ __forceinline__ void mma16816(float* c, const uint32_t* a, uint32_t b0, uint32_t b1) {
    asm volatile(
        "mma.sync.aligned.m16n8k16.row.col.f32.bf16.bf16.f32 "
        "{%0,%1,%2,%3}, {%4,%5,%6,%7}, {%8,%9}, {%0,%1,%2,%3};\n"
        : "+f"(c[0]), "+f"(c[1]), "+f"(c[2]), "+f"(c[3])
        : "r"(a[0]), "r"(a[1]), "r"(a[2]), "r"(a[3]), "r"(b0), "r"(b1));
}
__device__ __forceinline__ int chunk_owner(int L) {
    return (L < BIGLIN) ? (L / BIGCHUNK) : NBIG + (L - BIGLIN) / (BIGCHUNK - 1);
}

// ---------------- kernel 1: row-normalize -> bf16 ----------------
__global__ void normalize_kernel(const float* __restrict__ z1, const float* __restrict__ z2) {
    int warp = threadIdx.x >> 5, lane = threadIdx.x & 31;
    int row = blockIdx.x * 8 + warp;
    const float* src = (row < NHALF) ? (z1 + (size_t)row * DK)
                                     : (z2 + (size_t)(row - NHALF) * DK);
    float4 v0 = ((const float4*)src)[lane];
    float4 v1 = ((const float4*)src)[lane + 32];
    float ss = v0.x*v0.x + v0.y*v0.y + v0.z*v0.z + v0.w*v0.w
             + v1.x*v1.x + v1.y*v1.y + v1.z*v1.z + v1.w*v1.w;
    #pragma unroll
    for (int o = 16; o > 0; o >>= 1) ss += __shfl_xor_sync(0xffffffffu, ss, o);
    float rn = 1.0f / fmaxf(sqrtf(ss), 1e-6f);
    if (lane == 0) g_rnorm[row] = rn;

    __nv_bfloat162 w0a = __floats2bfloat162_rn(v0.x * rn, v0.y * rn);
    __nv_bfloat162 w0b = __floats2bfloat162_rn(v0.z * rn, v0.w * rn);
    __nv_bfloat162 w1a = __floats2bfloat162_rn(v1.x * rn, v1.y * rn);
    __nv_bfloat162 w1b = __floats2bfloat162_rn(v1.z * rn, v1.w * rn);
    uint2 p0, p1;
    memcpy(&p0.x, &w0a, 4); memcpy(&p0.y, &w0b, 4);
    memcpy(&p1.x, &w1a, 4); memcpy(&p1.y, &w1b, 4);
    uint2* dst = (uint2*)(g_zn + (size_t)row * DK);
    dst[lane]      = p0;
    dst[lane + 32] = p1;
}

// ---------------- kernel 2: fp32 positives ----------------
__global__ void pos_kernel(const float* __restrict__ z1, const float* __restrict__ z2) {
    int warp = threadIdx.x >> 5, lane = threadIdx.x & 31;
    int i = blockIdx.x * 8 + warp;
    const float* a = z1 + (size_t)i * DK;
    const float* b = z2 + (size_t)i * DK;
    float4 a0 = ((const float4*)a)[lane];
    float4 a1 = ((const float4*)a)[lane + 32];
    float4 b0 = ((const float4*)b)[lane];
    float4 b1 = ((const float4*)b)[lane + 32];
    float d = a0.x*b0.x + a0.y*b0.y + a0.z*b0.z + a0.w*b0.w
            + a1.x*b1.x + a1.y*b1.y + a1.z*b1.z + a1.w*b1.w;
    #pragma unroll
    for (int o = 16; o > 0; o >>= 1) d += __shfl_xor_sync(0xffffffffu, d, o);
    if (lane == 0) {
        float p = d * g_rnorm[i] * g_rnorm[i + NHALF];
        p = fminf(fmaxf(p, -1.0f + 1e-6f), 1.0f - 1e-6f);
        g_pos[i] = p;
    }
}

// ---------------- kernel 2b: zero g_bandparts ----------------
__global__ void zero_bp_kernel() {
    int i = blockIdx.x * 256 + threadIdx.x;    // 96 blocks * 256 * 4 = 98304 floats
    ((float4*)g_bandparts)[i] = make_float4(0.f, 0.f, 0.f, 0.f);
}

// ---------------- fused tile step: MMA(cur) + pipelined epilogue(prev) ----------------
// 8 warps x (64x32): 4 A ldsm + 2 B ldsm feed 16 MMAs per ks; 4 prev elems per ks.
__device__ __forceinline__ void pp_step(
    uint32_t sA, uint32_t sBc,
    const uint32_t (&aOffs)[4], uint32_t bOff, uint32_t bOff2,
    float (&cur)[4][4][4], float (&prev)[4][4][4],
    bool hasPrev, bool pdiag,
    float (&racc)[8], float (&cc8)[8],
    int rbase, int cbase)
{
    #pragma unroll
    for (int ks = 0; ks < 16; ++ks) {
        const uint32_t kb = (uint32_t)(ks * 32);
        uint32_t af[4][4], bA[4], bB[4];
        ldsm4(af[0], sA + aOffs[0] + kb);
        ldsm4(af[1], sA + aOffs[1] + kb);
        ldsm4(af[2], sA + aOffs[2] + kb);
        ldsm4(af[3], sA + aOffs[3] + kb);
        ldsm4(bA, sBc + bOff + kb);
        ldsm4(bB, sBc + bOff2 + kb);

        #pragma unroll
        for (int mf = 0; mf < 4; ++mf) {
            mma16816(cur[mf][0], af[mf], bA[0], bA[2]);
            mma16816(cur[mf][1], af[mf], bA[1], bA[3]);
            mma16816(cur[mf][2], af[mf], bB[0], bB[2]);
            mma16816(cur[mf][3], af[mf], bB[1], bB[3]);
        }

        if (hasPrev) {
            #pragma unroll
            for (int u = 0; u < 4; ++u) {
                const int idx = ks * 4 + u;
                const int mf = idx >> 4, nf = (idx >> 2) & 3, q = idx & 3;
                float v = prev[mf][nf][q];
                prev[mf][nf][q] = 0.f;
                float e = fast_ex2(v * SCALE_L2E);
                if (pdiag) {
                    int rl = rbase + mf * 16 + (q >> 1) * 8;
                    int cl = cbase + nf * 8 + (q & 1);
                    if (rl == cl) e = 0.f;
                }
                racc[mf * 2 + (q >> 1)] += e;
                cc8[nf * 2 + (q & 1)] += e;
            }
        }
    }
}

// drain epilogue for the final tile of a segment (zeroes the buffer)
__device__ __forceinline__ void pp_drain(
    float (&prev)[4][4][4], bool pdiag,
    float (&racc)[8], float (&cc8)[8], int rbase, int cbase)
{
    #pragma unroll
    for (int idx = 0; idx < 64; ++idx) {
        const int mf = idx >> 4, nf = (idx >> 2) & 3, q = idx & 3;
        float v = prev[mf][nf][q];
        prev[mf][nf][q] = 0.f;
        float e = fast_ex2(v * SCALE_L2E);
        if (pdiag) {
            int rl = rbase + mf * 16 + (q >> 1) * 8;
            int cl = cbase + nf * 8 + (q & 1);
            if (rl == cl) e = 0.f;
        }
        racc[mf * 2 + (q >> 1)] += e;
        cc8[nf * 2 + (q & 1)] += e;
    }
}

// reduce cc8 across lanes, store column sums for tile (band, t), reset cc8
__device__ __forceinline__ void flush_cc8(
    float (&cc8)[8], int band, int wm, int t, int wn, int tg, int g)
{
    #pragma unroll
    for (int j = 0; j < 8; ++j) {
        cc8[j] += __shfl_xor_sync(0xffffffffu, cc8[j], 4);
        cc8[j] += __shfl_xor_sync(0xffffffffu, cc8[j], 8);
        cc8[j] += __shfl_xor_sync(0xffffffffu, cc8[j], 16);
    }
    if (g == 0) {
        float* dst = g_cs + (size_t)(band * 2 + wm) * TWO_N + t * NT + wn * 32 + tg * 2;
        #pragma unroll
        for (int j = 0; j < 8; ++j) dst[(j >> 1) * 8 + (j & 1)] = cc8[j];
    }
    #pragma unroll
    for (int j = 0; j < 8; ++j) cc8[j] = 0.f;
}

// ---------------- kernel 3: symmetric HMMA sim-GEMM, ping-pong epilogue ----------------
__global__ __launch_bounds__(NTHREADS, 1) void simloss_pp() {
    extern __shared__ char smem_raw[];
    const uint32_t sbase = smem_u32(smem_raw);
    const uint32_t sA  = sbase + SM_A;
    const uint32_t sB0 = sbase + SM_B;

    const int tid  = threadIdx.x;
    const int lane = tid & 31;
    const int w    = tid >> 5;
    const int wm   = w >> 2;       // 0..1 : rows wm*64 .. +64
    const int wn   = w & 3;        // 0..3 : cols wn*32 .. +32
    const int g    = lane >> 2;
    const int tg   = lane & 3;
    const int rbase = wm * 64 + g;
    const int cbase = wn * 32 + tg * 2;

    const int cta = blockIdx.x;
    const int s_lin = (cta < NBIG) ? cta * BIGCHUNK : BIGLIN + (cta - NBIG) * (BIGCHUNK - 1);
    const int e_lin = s_lin + ((cta < NBIG) ? BIGCHUNK : (BIGCHUNK - 1));

    // ldmatrix per-lane offsets
    const int lrow = lane & 15;
    const int lchk = lane >> 4;
    uint32_t aOffs[4];
    #pragma unroll
    for (int mf = 0; mf < 4; ++mf)
        aOffs[mf] = (uint32_t)(((wm * 64 + mf * 16 + lrow) * SAPAD + lchk * 8) * 2);
    const uint32_t bOff  = (uint32_t)(((wn * 32 + lrow) * SAPAD + lchk * 8) * 2);
    const uint32_t bOff2 = bOff + (uint32_t)(16 * SAPAD * 2);

    float* sred = (float*)smem_raw;   // 512 floats scratch

    float accP[4][4][4], accQ[4][4][4];
    #pragma unroll
    for (int mf = 0; mf < 4; ++mf)
        #pragma unroll
        for (int nf = 0; nf < 4; ++nf)
            #pragma unroll
            for (int q = 0; q < 4; ++q) { accP[mf][nf][q] = 0.f; accQ[mf][nf][q] = 0.f; }
    float cc8[8];
    #pragma unroll
    for (int j = 0; j < 8; ++j) cc8[j] = 0.f;

    int idx = s_lin;
    while (idx < e_lin) {
        // ---- map linear idx -> (band, tile t0) via snake order ----
        int cum = 0, band = 0;
        #pragma unroll 1
        for (int j = 0; j < 128; ++j) {
            int bb = (j & 1) ? (127 - (j >> 1)) : (j >> 1);
            int sz = 128 - bb;
            if (idx < cum + sz) { band = bb; break; }
            cum += sz;
        }
        const int t0 = band + (idx - cum);
        int t1 = t0 + (e_lin - idx) - 1;
        if (t1 > 127) t1 = 127;
        const int nb = t1 - t0 + 1;
        const int slot = cta - chunk_owner(cum);

        // ---- load A(band) + B(t0) ----
        {
            const __nv_bfloat16* gA = g_zn + (size_t)band * MT * DK;
            const __nv_bfloat16* gB = g_zn + (size_t)t0 * NT * DK;
            #pragma unroll
            for (int k = 0; k < 16; ++k) {
                int id = tid + k * NTHREADS;
                int r = id >> 5, c = id & 31;
                uint32_t so = (uint32_t)((r * SAPAD + c * 8) * 2);
                cp16(sA + so, gA + (size_t)r * DK + c * 8);
                cp16(sB0 + so, gB + (size_t)r * DK + c * 8);
            }
            cp_commit(); cp_wait0();
        }
        __syncthreads();

        float racc[8];
        #pragma unroll
        for (int j = 0; j < 8; ++j) racc[j] = 0.f;

        for (int i2 = 0; i2 < nb; ++i2) {
            const int t = t0 + i2;
            const uint32_t sBc = sB0 + (uint32_t)((i2 & 1) * TILE_BYTES2);

            if (i2 + 1 < nb) {
                const uint32_t sBn = sB0 + (uint32_t)(((i2 + 1) & 1) * TILE_BYTES2);
                const __nv_bfloat16* gB = g_zn + (size_t)(t + 1) * NT * DK;
                #pragma unroll
                for (int k = 0; k < 16; ++k) {
                    int id = tid + k * NTHREADS;
                    int r = id >> 5, c = id & 31;
                    cp16(sBn + (uint32_t)((r * SAPAD + c * 8) * 2), gB + (size_t)r * DK + c * 8);
                }
            }
            cp_commit();

            const bool hasPrev = (i2 > 0);
            const int  pt = t - 1;
            const bool pdiag = hasPrev && (pt == band);

            if ((i2 & 1) == 0)
                pp_step(sA, sBc, aOffs, bOff, bOff2, accP, accQ,
                        hasPrev, pdiag, racc, cc8, rbase, cbase);
            else
                pp_step(sA, sBc, aOffs, bOff, bOff2, accQ, accP,
                        hasPrev, pdiag, racc, cc8, rbase, cbase);

            if (hasPrev) {
                if (!pdiag) flush_cc8(cc8, band, wm, pt, wn, tg, g);
                else {
                    #pragma unroll
                    for (int j = 0; j < 8; ++j) cc8[j] = 0.f;
                }
            }

            cp_wait0();
            __syncthreads();
        }

        // ---- drain last tile of segment ----
        {
            const int lt = t0 + nb - 1;
            const bool pdiag = (lt == band);
            if (((nb - 1) & 1) == 0)
                pp_drain(accP, pdiag, racc, cc8, rbase, cbase);
            else
                pp_drain(accQ, pdiag, racc, cc8, rbase, cbase);
            if (!pdiag) flush_cc8(cc8, band, wm, lt, wn, tg, g);
            else {
                #pragma unroll
                for (int j = 0; j < 8; ++j) cc8[j] = 0.f;
            }
        }

        // ---- flush row partials for this band segment ----
        #pragma unroll
        for (int k2 = 0; k2 < 8; ++k2) {
            racc[k2] += __shfl_xor_sync(0xffffffffu, racc[k2], 1);
            racc[k2] += __shfl_xor_sync(0xffffffffu, racc[k2], 2);
        }
        if (tg == 0) {
            #pragma unroll
            for (int mf = 0; mf < 4; ++mf)
                #pragma unroll
                for (int h = 0; h < 2; ++h)
                    sred[wn * 128 + wm * 64 + mf * 16 + h * 8 + g] = racc[mf * 2 + h];
        }
        __syncthreads();
        if (tid < 128) {
            g_bandparts[(band * NSLOT + slot) * 128 + tid] =
                sred[tid] + sred[128 + tid] + sred[256 + tid] + sred[384 + tid];
        }
        __syncthreads();

        idx += nb;
    }
}

// ---------------- kernel 3b: combine partials + transposed column sums, take log ----------------
__global__ void rowfinal_kernel() {
    __shared__ float sm[512];
    const int B = blockIdx.x;
    const int rl = threadIdx.x & 127;
    const int chunk = threadIdx.x >> 7;
    const int r = B * 128 + rl;
    float sacc = 0.f;
    for (int b = chunk; b < B; b += 4) {
        const float* p2 = g_cs + (size_t)(b * 2) * TWO_N + r;
        sacc += p2[0] + p2[TWO_N];
    }
    sm[threadIdx.x] = sacc;
    __syncthreads();
    if (chunk == 0) {
        float tot = sm[rl] + sm[rl + 128] + sm[rl + 256] + sm[rl + 384];
        const float* bp = g_bandparts + (size_t)B * NSLOT * 128 + rl;
        #pragma unroll
        for (int s = 0; s < NSLOT; ++s) tot += bp[s * 128];
        g_rowsum[r] = logf(tot);
    }
}

// ---------------- kernel 4: two-stage final reduce ----------------
__global__ void reduce1_kernel() {
    __shared__ float sa[256], sb[256];
    int b = blockIdx.x, tid = threadIdx.x;
    float a = g_rowsum[b * 256 + tid];          // already log
    float pp = (tid < 128) ? g_pos[b * 128 + tid] : 0.f;
    sa[tid] = a; sb[tid] = pp;
    __syncthreads();
    for (int s = 128; s > 0; s >>= 1) {
        if (tid < s) { sa[tid] += sa[tid + s]; sb[tid] += sb[tid + s]; }
        __syncthreads();
    }
    if (tid == 0) { g_partA[b] = sa[0]; g_partB[b] = sb[0]; }
}

__global__ void reduce2_kernel(float* __restrict__ out) {
    __shared__ float sa[64], sb[64];
    int tid = threadIdx.x;
    sa[tid] = g_partA[tid]; sb[tid] = g_partB[tid];
    __syncthreads();
    for (int s = 32; s > 0; s >>= 1) {
        if (tid < s) { sa[tid] += sa[tid + s]; sb[tid] += sb[tid + s]; }
        __syncthreads();
    }
    if (tid == 0) out[0] = (sa[0] - 20.0f * sb[0]) / (float)TWO_N;
}

// ---------------- launch ----------------
extern "C" void kernel_launch(void* const* d_in, const int* in_sizes, int n_in,
                              void* d_out, int out_size) {
    const float* z1 = (const float*)d_in[0];
    const float* z2 = (const float*)d_in[1];
    float* out = (float*)d_out;

    normalize_kernel<<<2048, 256>>>(z1, z2);
    pos_kernel<<<1024, 256>>>(z1, z2);
    zero_bp_kernel<<<96, 256>>>();
    cudaFuncSetAttribute(simloss_pp, cudaFuncAttributeMaxDynamicSharedMemorySize, SMEM_BYTES);
    simloss_pp<<<NCTA, NTHREADS, SMEM_BYTES>>>();
    rowfinal_kernel<<<128, 512>>>();
    reduce1_kernel<<<64, 256>>>();
    reduce2_kernel<<<1, 64>>>(out);
}

// round 12
// speedup vs baseline: 1.2509x; 1.1135x over previous
#include <cuda_runtime.h>
#include <cuda_bf16.h>
#include <cstdint>

// ---------------- problem constants ----------------
#define TWO_N   16384
#define NHALF   8192
#define DK      256
#define MT      128
#define NT      128
#define SAPAD   264      // padded smem row stride in bf16 (528B; conflict-free ldmatrix)
#define TILE_BYTES2 (MT * SAPAD * 2)

// tile-list scheduling: 8256 upper-tri tiles over 148 CTAs
#define NCTA    148
#define BIGCHUNK 56
#define NBIG    116          // 116*56 + 32*55 = 8256
#define BIGLIN  (NBIG * BIGCHUNK)   // 6496
#define NSLOT   6

// smem: scratch (2KB) | A tile | B tile x2
#define SM_A       2048
#define SM_B       (SM_A + TILE_BYTES2)
#define SMEM_BYTES (SM_B + 2 * TILE_BYTES2)   // 204800 B

#define SCALE_L2E 14.426950408889634f   // 10 * log2(e)

// ---------------- device scratch ----------------
__device__ __align__(16) __nv_bfloat16 g_zn[TWO_N * DK];
__device__ float g_pos[NHALF];
__device__ float g_partA[128];
__device__ float g_partB[128];
// column-sum contributions: [band(writer) * 4 + wm][col]  (32 MB, single-writer per tile)
__device__ float g_cs[128 * 4 * TWO_N];
// row partials: [band][slot][row]  (zeroed each run; single writer per slot)
__device__ float g_bandparts[128 * NSLOT * 128];

// ---------------- helpers ----------------
__device__ __forceinline__ float fast_ex2(float x) {
    float y;
    asm("ex2.approx.f32 %0, %1;" : "=f"(y) : "f"(x));
    return y;
}
__device__ __forceinline__ uint32_t smem_u32(const void* p) {
    uint32_t a;
    asm("{ .reg .u64 t; cvta.to.shared.u64 t, %1; cvt.u32.u64 %0, t; }" : "=r"(a) : "l"(p));
    return a;
}
__device__ __forceinline__ void cp16(uint32_t dst, const void* src) {
    asm volatile("cp.async.cg.shared.global [%0], [%1], 16;\n" :: "r"(dst), "l"(src));
}
__device__ __forceinline__ void cp_commit() { asm volatile("cp.async.commit_group;\n"); }
__device__ __forceinline__ void cp_wait0()  { asm volatile("cp.async.wait_group 0;\n"); }

__device__ __forceinline__ void ldsm4(uint32_t* r, uint32_t addr) {
    asm volatile("ldmatrix.sync.aligned.m8n8.x4.shared.b16 {%0,%1,%2,%3}, [%4];"
                 : "=r"(r[0]), "=r"(r[1]), "=r"(r[2]), "=r"(r[3]) : "r"(addr));
}
__device__ __forceinline__ void mma16816(float* c, const uint32_t* a, uint32_t b0, uint32_t b1) {
    asm volatile(
        "mma.sync.aligned.m16n8k16.row.col.f32.bf16.bf16.f32 "
        "{%0,%1,%2,%3}, {%4,%5,%6,%7}, {%8,%9}, {%0,%1,%2,%3};\n"
        : "+f"(c[0]), "+f"(c[1]), "+f"(c[2]), "+f"(c[3])
        : "r"(a[0]), "r"(a[1]), "r"(a[2]), "r"(a[3]), "r"(b0), "r"(b1));
}
__device__ __forceinline__ int chunk_owner(int L) {
    return (L < BIGLIN) ? (L / BIGCHUNK) : NBIG + (L - BIGLIN) / (BIGCHUNK - 1);
}

// ---------------- kernel 1: fused row-normalize (both views) + fp32 positives ----------------
// grid 1024 x 256: one warp per pair i in [0, NHALF)
__global__ void normpos_kernel(const float* __restrict__ z1, const float* __restrict__ z2) {
    int warp = threadIdx.x >> 5, lane = threadIdx.x & 31;
    int i = blockIdx.x * 8 + warp;
    const float* a = z1 + (size_t)i * DK;
    const float* b = z2 + (size_t)i * DK;
    float4 a0 = ((const float4*)a)[lane];
    float4 a1 = ((const float4*)a)[lane + 32];
    float4 b0 = ((const float4*)b)[lane];
    float4 b1 = ((const float4*)b)[lane + 32];

    float ss1 = a0.x*a0.x + a0.y*a0.y + a0.z*a0.z + a0.w*a0.w
              + a1.x*a1.x + a1.y*a1.y + a1.z*a1.z + a1.w*a1.w;
    float ss2 = b0.x*b0.x + b0.y*b0.y + b0.z*b0.z + b0.w*b0.w
              + b1.x*b1.x + b1.y*b1.y + b1.z*b1.z + b1.w*b1.w;
    float d   = a0.x*b0.x + a0.y*b0.y + a0.z*b0.z + a0.w*b0.w
              + a1.x*b1.x + a1.y*b1.y + a1.z*b1.z + a1.w*b1.w;
    #pragma unroll
    for (int o = 16; o > 0; o >>= 1) {
        ss1 += __shfl_xor_sync(0xffffffffu, ss1, o);
        ss2 += __shfl_xor_sync(0xffffffffu, ss2, o);
        d   += __shfl_xor_sync(0xffffffffu, d, o);
    }
    float rn1 = 1.0f / fmaxf(sqrtf(ss1), 1e-6f);
    float rn2 = 1.0f / fmaxf(sqrtf(ss2), 1e-6f);
    if (lane == 0) {
        float p = d * rn1 * rn2;
        p = fminf(fmaxf(p, -1.0f + 1e-6f), 1.0f - 1e-6f);
        g_pos[i] = p;
    }

    // write normalized bf16 row i (from z1) and row i+NHALF (from z2)
    {
        __nv_bfloat162 w0 = __floats2bfloat162_rn(a0.x * rn1, a0.y * rn1);
        __nv_bfloat162 w1 = __floats2bfloat162_rn(a0.z * rn1, a0.w * rn1);
        __nv_bfloat162 w2 = __floats2bfloat162_rn(a1.x * rn1, a1.y * rn1);
        __nv_bfloat162 w3 = __floats2bfloat162_rn(a1.z * rn1, a1.w * rn1);
        uint2 p0, p1;
        memcpy(&p0.x, &w0, 4); memcpy(&p0.y, &w1, 4);
        memcpy(&p1.x, &w2, 4); memcpy(&p1.y, &w3, 4);
        uint2* dst = (uint2*)(g_zn + (size_t)i * DK);
        dst[lane]      = p0;
        dst[lane + 32] = p1;
    }
    {
        __nv_bfloat162 w0 = __floats2bfloat162_rn(b0.x * rn2, b0.y * rn2);
        __nv_bfloat162 w1 = __floats2bfloat162_rn(b0.z * rn2, b0.w * rn2);
        __nv_bfloat162 w2 = __floats2bfloat162_rn(b1.x * rn2, b1.y * rn2);
        __nv_bfloat162 w3 = __floats2bfloat162_rn(b1.z * rn2, b1.w * rn2);
        uint2 p0, p1;
        memcpy(&p0.x, &w0, 4); memcpy(&p0.y, &w1, 4);
        memcpy(&p1.x, &w2, 4); memcpy(&p1.y, &w3, 4);
        uint2* dst = (uint2*)(g_zn + (size_t)(i + NHALF) * DK);
        dst[lane]      = p0;
        dst[lane + 32] = p1;
    }
}

// ---------------- kernel 1b: zero g_bandparts ----------------
__global__ void zero_bp_kernel() {
    int i = blockIdx.x * 256 + threadIdx.x;    // 96 blocks * 256 * 4 = 98304 floats
    ((float4*)g_bandparts)[i] = make_float4(0.f, 0.f, 0.f, 0.f);
}

// ---------------- kernel 2: symmetric HMMA sim-GEMM (R5 config, verbatim) ----------------
__global__ __launch_bounds__(512, 1) void simloss_sym2() {
    extern __shared__ char smem_raw[];
    const uint32_t sbase = smem_u32(smem_raw);
    const uint32_t sA  = sbase + SM_A;
    const uint32_t sB0 = sbase + SM_B;

    const int tid  = threadIdx.x;
    const int lane = tid & 31;
    const int w    = tid >> 5;
    const int wm   = w >> 2;
    const int wn   = w & 3;
    const int g    = lane >> 2;
    const int tg   = lane & 3;

    const int cta = blockIdx.x;
    const int s_lin = (cta < NBIG) ? cta * BIGCHUNK : BIGLIN + (cta - NBIG) * (BIGCHUNK - 1);
    const int e_lin = s_lin + ((cta < NBIG) ? BIGCHUNK : (BIGCHUNK - 1));

    // ldmatrix per-lane offsets
    const int lrow = lane & 15;
    const int lchk = lane >> 4;
    const uint32_t aOff  = (uint32_t)(((wm * 32 + lrow) * SAPAD + lchk * 8) * 2);
    const uint32_t aOff2 = aOff + (uint32_t)(16 * SAPAD * 2);
    const uint32_t bOff  = (uint32_t)(((wn * 32 + lrow) * SAPAD + lchk * 8) * 2);
    const uint32_t bOff2 = bOff + (uint32_t)(16 * SAPAD * 2);

    float* sred = (float*)smem_raw;            // 512 floats scratch

    int idx = s_lin;
    while (idx < e_lin) {
        // ---- map linear idx -> (band, tile t0) via snake order ----
        int cum = 0, band = 0;
        #pragma unroll 1
        for (int j = 0; j < 128; ++j) {
            int bb = (j & 1) ? (127 - (j >> 1)) : (j >> 1);
            int sz = 128 - bb;
            if (idx < cum + sz) { band = bb; break; }
            cum += sz;
        }
        const int t0 = band + (idx - cum);
        int t1 = t0 + (e_lin - idx) - 1;
        if (t1 > 127) t1 = 127;
        const int nb = t1 - t0 + 1;
        const int slot = cta - chunk_owner(cum);   // 0..NSLOT-1, single writer

        // ---- load A(band) + B(t0) ----
        {
            const __nv_bfloat16* gA = g_zn + (size_t)band * MT * DK;
            const __nv_bfloat16* gB = g_zn + (size_t)t0 * NT * DK;
            #pragma unroll
            for (int k = 0; k < 8; ++k) {
                int id = tid + k * 512;
                int r = id >> 5, ccx = id & 31;
                uint32_t so = (uint32_t)((r * SAPAD + ccx * 8) * 2);
                cp16(sA + so, gA + (size_t)r * DK + ccx * 8);
                cp16(sB0 + so, gB + (size_t)r * DK + ccx * 8);
            }
            cp_commit(); cp_wait0();
        }
        __syncthreads();

        float acc[2][4][4];
        #pragma unroll
        for (int mf = 0; mf < 2; ++mf)
            #pragma unroll
            for (int nf = 0; nf < 4; ++nf)
                #pragma unroll
                for (int q = 0; q < 4; ++q) acc[mf][nf][q] = 0.f;
        float racc[4] = {0.f, 0.f, 0.f, 0.f};

        for (int i2 = 0; i2 < nb; ++i2) {
            const int t = t0 + i2;
            const uint32_t sBc = sB0 + (uint32_t)((i2 & 1) * TILE_BYTES2);

            if (i2 + 1 < nb) {
                const uint32_t sBn = sB0 + (uint32_t)(((i2 + 1) & 1) * TILE_BYTES2);
                const __nv_bfloat16* gB = g_zn + (size_t)(t + 1) * NT * DK;
                #pragma unroll
                for (int k = 0; k < 8; ++k) {
                    int id = tid + k * 512;
                    int r = id >> 5, ccx = id & 31;
                    cp16(sBn + (uint32_t)((r * SAPAD + ccx * 8) * 2), gB + (size_t)r * DK + ccx * 8);
                }
            }
            cp_commit();

            #pragma unroll
            for (int ks = 0; ks < 16; ++ks) {
                const uint32_t kb = (uint32_t)(ks * 32);
                uint32_t a0[4], a1[4], bA[4], bB[4];
                ldsm4(a0, sA + aOff + kb);
                ldsm4(a1, sA + aOff2 + kb);
                ldsm4(bA, sBc + bOff + kb);
                ldsm4(bB, sBc + bOff2 + kb);

                mma16816(acc[0][0], a0, bA[0], bA[2]);
                mma16816(acc[1][0], a1, bA[0], bA[2]);
                mma16816(acc[0][1], a0, bA[1], bA[3]);
                mma16816(acc[1][1], a1, bA[1], bA[3]);
                mma16816(acc[0][2], a0, bB[0], bB[2]);
                mma16816(acc[1][2], a1, bB[0], bB[2]);
                mma16816(acc[0][3], a0, bB[1], bB[3]);
                mma16816(acc[1][3], a1, bB[1], bB[3]);
            }

            // ---- epilogue: exp, row accumulate, column accumulate (symmetry) ----
            const bool offd = (t != band);
            float cc8[8];
            #pragma unroll
            for (int j = 0; j < 8; ++j) cc8[j] = 0.f;

            #pragma unroll
            for (int mf = 0; mf < 2; ++mf)
                #pragma unroll
                for (int nf = 0; nf < 4; ++nf)
                    #pragma unroll
                    for (int q = 0; q < 4; ++q) {
                        float e = fast_ex2(acc[mf][nf][q] * SCALE_L2E);
                        if (!offd) {
                            int rl = wm * 32 + mf * 16 + (q >> 1) * 8 + g;
                            int cl = wn * 32 + nf * 8 + tg * 2 + (q & 1);
                            if (rl == cl) e = 0.f;
                        }
                        racc[mf * 2 + (q >> 1)] += e;
                        cc8[nf * 2 + (q & 1)] += e;
                        acc[mf][nf][q] = 0.f;
                    }

            if (offd) {
                #pragma unroll
                for (int j = 0; j < 8; ++j) {
                    cc8[j] += __shfl_xor_sync(0xffffffffu, cc8[j], 4);
                    cc8[j] += __shfl_xor_sync(0xffffffffu, cc8[j], 8);
                    cc8[j] += __shfl_xor_sync(0xffffffffu, cc8[j], 16);
                }
                if (g == 0) {
                    float* dst = g_cs + (size_t)(band * 4 + wm) * TWO_N
                               + t * NT + wn * 32 + tg * 2;
                    #pragma unroll
                    for (int j = 0; j < 8; ++j) dst[(j >> 1) * 8 + (j & 1)] = cc8[j];
                }
            }

            cp_wait0();
            __syncthreads();
        }

        // ---- flush row partials for this band segment ----
        #pragma unroll
        for (int k2 = 0; k2 < 4; ++k2) {
            racc[k2] += __shfl_xor_sync(0xffffffffu, racc[k2], 1);
            racc[k2] += __shfl_xor_sync(0xffffffffu, racc[k2], 2);
        }
        if (tg == 0) {
            #pragma unroll
            for (int mf = 0; mf < 2; ++mf)
                #pragma unroll
                for (int h = 0; h < 2; ++h)
                    sred[wn * 128 + wm * 32 + mf * 16 + h * 8 + g] = racc[mf * 2 + h];
        }
        __syncthreads();
        if (tid < 128) {
            g_bandparts[(band * NSLOT + slot) * 128 + tid] =
                sred[tid] + sred[128 + tid] + sred[256 + tid] + sred[384 + tid];
        }
        __syncthreads();

        idx += nb;
    }
}

// ---------------- kernel 3: rowsum assembly + log + per-band loss partials ----------------
// grid 128 x 512: band B = blockIdx.x; chunks split the b' loop; then block-reduce
// log-sum and pos-sum to g_partA/g_partB (reduce1 folded in; g_rowsum eliminated).
__global__ void rowfinal_kernel() {
    __shared__ float sm[512];
    __shared__ float sl[128];
    __shared__ float sp[128];
    const int B = blockIdx.x;
    const int rl = threadIdx.x & 127;
    const int chunk = threadIdx.x >> 7;
    const int r = B * 128 + rl;
    float sacc = 0.f;
    for (int b = chunk; b < B; b += 4) {
        const float* p4 = g_cs + (size_t)(b * 4) * TWO_N + r;
        sacc += p4[0] + p4[TWO_N] + p4[2 * TWO_N] + p4[3 * TWO_N];
    }
    sm[threadIdx.x] = sacc;
    if (chunk == 1) sp[rl] = (B < 64) ? g_pos[B * 128 + rl] : 0.f;
    __syncthreads();
    if (chunk == 0) {
        float tot = sm[rl] + sm[rl + 128] + sm[rl + 256] + sm[rl + 384];
        const float* bp = g_bandparts + (size_t)B * NSLOT * 128 + rl;
        #pragma unroll
        for (int s = 0; s < NSLOT; ++s) tot += bp[s * 128];
        sl[rl] = logf(tot);
    }
    __syncthreads();
    // block-reduce the 128 log values and 128 pos values
    for (int s = 64; s > 0; s >>= 1) {
        if (threadIdx.x < s) {
            sl[threadIdx.x] += sl[threadIdx.x + s];
            sp[threadIdx.x] += sp[threadIdx.x + s];
        }
        __syncthreads();
    }
    if (threadIdx.x == 0) { g_partA[B] = sl[0]; g_partB[B] = sp[0]; }
}

// ---------------- kernel 4: final reduce over 128 partials ----------------
__global__ void reduce2_kernel(float* __restrict__ out) {
    __shared__ float sa[128], sb[128];
    int tid = threadIdx.x;
    sa[tid] = g_partA[tid]; sb[tid] = g_partB[tid];
    __syncthreads();
    for (int s = 64; s > 0; s >>= 1) {
        if (tid < s) { sa[tid] += sa[tid + s]; sb[tid] += sb[tid + s]; }
        __syncthreads();
    }
    if (tid == 0) out[0] = (sa[0] - 20.0f * sb[0]) / (float)TWO_N;
}

// ---------------- launch ----------------
extern "C" void kernel_launch(void* const* d_in, const int* in_sizes, int n_in,
                              void* d_out, int out_size) {
    const float* z1 = (const float*)d_in[0];
    const float* z2 = (const float*)d_in[1];
    float* out = (float*)d_out;

    normpos_kernel<<<1024, 256>>>(z1, z2);
    zero_bp_kernel<<<96, 256>>>();
    cudaFuncSetAttribute(simloss_sym2, cudaFuncAttributeMaxDynamicSharedMemorySize, SMEM_BYTES);
    simloss_sym2<<<NCTA, 512, SMEM_BYTES>>>();
    rowfinal_kernel<<<128, 512>>>();
    reduce2_kernel<<<1, 128>>>(out);
}

// round 13
// speedup vs baseline: 1.2562x; 1.0043x over previous
#include <cuda_runtime.h>
#include <cuda_bf16.h>
#include <cstdint>

// ---------------- problem constants ----------------
#define TWO_N   16384
#define NHALF   8192
#define DK      256
#define MT      128
#define NT      128
#define SAPAD   264      // padded smem row stride in bf16 (528B; conflict-free ldmatrix)
#define TILE_BYTES2 (MT * SAPAD * 2)

// tile-list scheduling: 8256 upper-tri tiles over 148 CTAs
#define NCTA    148
#define BIGCHUNK 56
#define NBIG    116          // 116*56 + 32*55 = 8256
#define BIGLIN  (NBIG * BIGCHUNK)   // 6496
#define NSLOT   6

// smem: scratch (2KB) | A tile | B tile x2
#define SM_A       2048
#define SM_B       (SM_A + TILE_BYTES2)
#define SMEM_BYTES (SM_B + 2 * TILE_BYTES2)   // 204800 B

#define SCALE_L2E 14.426950408889634f   // 10 * log2(e)

// ---------------- device scratch ----------------
__device__ __align__(16) __nv_bfloat16 g_zn[TWO_N * DK];
__device__ float g_pos[NHALF];
__device__ float g_partA[256];
__device__ float g_partB[256];
// column-sum contributions: [band(writer) * 4 + wm][col]  (32 MB, single-writer per tile)
__device__ float g_cs[128 * 4 * TWO_N];
// row partials: [band][slot][row]  (zeroed each run; single writer per slot)
__device__ float g_bandparts[128 * NSLOT * 128];

// ---------------- helpers ----------------
__device__ __forceinline__ float fast_ex2(float x) {
    float y;
    asm("ex2.approx.f32 %0, %1;" : "=f"(y) : "f"(x));
    return y;
}
__device__ __forceinline__ uint32_t smem_u32(const void* p) {
    uint32_t a;
    asm("{ .reg .u64 t; cvta.to.shared.u64 t, %1; cvt.u32.u64 %0, t; }" : "=r"(a) : "l"(p));
    return a;
}
__device__ __forceinline__ void cp16(uint32_t dst, const void* src) {
    asm volatile("cp.async.cg.shared.global [%0], [%1], 16;\n" :: "r"(dst), "l"(src));
}
__device__ __forceinline__ void cp_commit() { asm volatile("cp.async.commit_group;\n"); }
__device__ __forceinline__ void cp_wait0()  { asm volatile("cp.async.wait_group 0;\n"); }

__device__ __forceinline__ void ldsm4(uint32_t* r, uint32_t addr) {
    asm volatile("ldmatrix.sync.aligned.m8n8.x4.shared.b16 {%0,%1,%2,%3}, [%4];"
                 : "=r"(r[0]), "=r"(r[1]), "=r"(r[2]), "=r"(r[3]) : "r"(addr));
}
__device__ __forceinline__ void mma16816(float* c, const uint32_t* a, uint32_t b0, uint32_t b1) {
    asm volatile(
        "mma.sync.aligned.m16n8k16.row.col.f32.bf16.bf16.f32 "
        "{%0,%1,%2,%3}, {%4,%5,%6,%7}, {%8,%9}, {%0,%1,%2,%3};\n"
        : "+f"(c[0]), "+f"(c[1]), "+f"(c[2]), "+f"(c[3])
        : "r"(a[0]), "r"(a[1]), "r"(a[2]), "r"(a[3]), "r"(b0), "r"(b1));
}
__device__ __forceinline__ int chunk_owner(int L) {
    return (L < BIGLIN) ? (L / BIGCHUNK) : NBIG + (L - BIGLIN) / (BIGCHUNK - 1);
}

// ---------------- kernel 1: fused row-normalize (both views) + fp32 positives ----------------
// grid 1024 x 256: one warp per pair i in [0, NHALF)
__global__ void normpos_kernel(const float* __restrict__ z1, const float* __restrict__ z2) {
    int warp = threadIdx.x >> 5, lane = threadIdx.x & 31;
    int i = blockIdx.x * 8 + warp;
    const float* a = z1 + (size_t)i * DK;
    const float* b = z2 + (size_t)i * DK;
    float4 a0 = ((const float4*)a)[lane];
    float4 a1 = ((const float4*)a)[lane + 32];
    float4 b0 = ((const float4*)b)[lane];
    float4 b1 = ((const float4*)b)[lane + 32];

    float ss1 = a0.x*a0.x + a0.y*a0.y + a0.z*a0.z + a0.w*a0.w
              + a1.x*a1.x + a1.y*a1.y + a1.z*a1.z + a1.w*a1.w;
    float ss2 = b0.x*b0.x + b0.y*b0.y + b0.z*b0.z + b0.w*b0.w
              + b1.x*b1.x + b1.y*b1.y + b1.z*b1.z + b1.w*b1.w;
    float d   = a0.x*b0.x + a0.y*b0.y + a0.z*b0.z + a0.w*b0.w
              + a1.x*b1.x + a1.y*b1.y + a1.z*b1.z + a1.w*b1.w;
    #pragma unroll
    for (int o = 16; o > 0; o >>= 1) {
        ss1 += __shfl_xor_sync(0xffffffffu, ss1, o);
        ss2 += __shfl_xor_sync(0xffffffffu, ss2, o);
        d   += __shfl_xor_sync(0xffffffffu, d, o);
    }
    float rn1 = 1.0f / fmaxf(sqrtf(ss1), 1e-6f);
    float rn2 = 1.0f / fmaxf(sqrtf(ss2), 1e-6f);
    if (lane == 0) {
        float p = d * rn1 * rn2;
        p = fminf(fmaxf(p, -1.0f + 1e-6f), 1.0f - 1e-6f);
        g_pos[i] = p;
    }

    {
        __nv_bfloat162 w0 = __floats2bfloat162_rn(a0.x * rn1, a0.y * rn1);
        __nv_bfloat162 w1 = __floats2bfloat162_rn(a0.z * rn1, a0.w * rn1);
        __nv_bfloat162 w2 = __floats2bfloat162_rn(a1.x * rn1, a1.y * rn1);
        __nv_bfloat162 w3 = __floats2bfloat162_rn(a1.z * rn1, a1.w * rn1);
        uint2 p0, p1;
        memcpy(&p0.x, &w0, 4); memcpy(&p0.y, &w1, 4);
        memcpy(&p1.x, &w2, 4); memcpy(&p1.y, &w3, 4);
        uint2* dst = (uint2*)(g_zn + (size_t)i * DK);
        dst[lane]      = p0;
        dst[lane + 32] = p1;
    }
    {
        __nv_bfloat162 w0 = __floats2bfloat162_rn(b0.x * rn2, b0.y * rn2);
        __nv_bfloat162 w1 = __floats2bfloat162_rn(b0.z * rn2, b0.w * rn2);
        __nv_bfloat162 w2 = __floats2bfloat162_rn(b1.x * rn2, b1.y * rn2);
        __nv_bfloat162 w3 = __floats2bfloat162_rn(b1.z * rn2, b1.w * rn2);
        uint2 p0, p1;
        memcpy(&p0.x, &w0, 4); memcpy(&p0.y, &w1, 4);
        memcpy(&p1.x, &w2, 4); memcpy(&p1.y, &w3, 4);
        uint2* dst = (uint2*)(g_zn + (size_t)(i + NHALF) * DK);
        dst[lane]      = p0;
        dst[lane + 32] = p1;
    }
}

// ---------------- kernel 1b: zero g_bandparts ----------------
__global__ void zero_bp_kernel() {
    int i = blockIdx.x * 256 + threadIdx.x;    // 96 blocks * 256 * 4 = 98304 floats
    ((float4*)g_bandparts)[i] = make_float4(0.f, 0.f, 0.f, 0.f);
}

// ---------------- kernel 2: symmetric HMMA sim-GEMM (R5 config, verbatim) ----------------
__global__ __launch_bounds__(512, 1) void simloss_sym2() {
    extern __shared__ char smem_raw[];
    const uint32_t sbase = smem_u32(smem_raw);
    const uint32_t sA  = sbase + SM_A;
    const uint32_t sB0 = sbase + SM_B;

    const int tid  = threadIdx.x;
    const int lane = tid & 31;
    const int w    = tid >> 5;
    const int wm   = w >> 2;
    const int wn   = w & 3;
    const int g    = lane >> 2;
    const int tg   = lane & 3;

    const int cta = blockIdx.x;
    const int s_lin = (cta < NBIG) ? cta * BIGCHUNK : BIGLIN + (cta - NBIG) * (BIGCHUNK - 1);
    const int e_lin = s_lin + ((cta < NBIG) ? BIGCHUNK : (BIGCHUNK - 1));

    const int lrow = lane & 15;
    const int lchk = lane >> 4;
    const uint32_t aOff  = (uint32_t)(((wm * 32 + lrow) * SAPAD + lchk * 8) * 2);
    const uint32_t aOff2 = aOff + (uint32_t)(16 * SAPAD * 2);
    const uint32_t bOff  = (uint32_t)(((wn * 32 + lrow) * SAPAD + lchk * 8) * 2);
    const uint32_t bOff2 = bOff + (uint32_t)(16 * SAPAD * 2);

    float* sred = (float*)smem_raw;            // 512 floats scratch

    int idx = s_lin;
    while (idx < e_lin) {
        int cum = 0, band = 0;
        #pragma unroll 1
        for (int j = 0; j < 128; ++j) {
            int bb = (j & 1) ? (127 - (j >> 1)) : (j >> 1);
            int sz = 128 - bb;
            if (idx < cum + sz) { band = bb; break; }
            cum += sz;
        }
        const int t0 = band + (idx - cum);
        int t1 = t0 + (e_lin - idx) - 1;
        if (t1 > 127) t1 = 127;
        const int nb = t1 - t0 + 1;
        const int slot = cta - chunk_owner(cum);   // 0..NSLOT-1, single writer

        {
            const __nv_bfloat16* gA = g_zn + (size_t)band * MT * DK;
            const __nv_bfloat16* gB = g_zn + (size_t)t0 * NT * DK;
            #pragma unroll
            for (int k = 0; k < 8; ++k) {
                int id = tid + k * 512;
                int r = id >> 5, ccx = id & 31;
                uint32_t so = (uint32_t)((r * SAPAD + ccx * 8) * 2);
                cp16(sA + so, gA + (size_t)r * DK + ccx * 8);
                cp16(sB0 + so, gB + (size_t)r * DK + ccx * 8);
            }
            cp_commit(); cp_wait0();
        }
        __syncthreads();

        float acc[2][4][4];
        #pragma unroll
        for (int mf = 0; mf < 2; ++mf)
            #pragma unroll
            for (int nf = 0; nf < 4; ++nf)
                #pragma unroll
                for (int q = 0; q < 4; ++q) acc[mf][nf][q] = 0.f;
        float racc[4] = {0.f, 0.f, 0.f, 0.f};

        for (int i2 = 0; i2 < nb; ++i2) {
            const int t = t0 + i2;
            const uint32_t sBc = sB0 + (uint32_t)((i2 & 1) * TILE_BYTES2);

            if (i2 + 1 < nb) {
                const uint32_t sBn = sB0 + (uint32_t)(((i2 + 1) & 1) * TILE_BYTES2);
                const __nv_bfloat16* gB = g_zn + (size_t)(t + 1) * NT * DK;
                #pragma unroll
                for (int k = 0; k < 8; ++k) {
                    int id = tid + k * 512;
                    int r = id >> 5, ccx = id & 31;
                    cp16(sBn + (uint32_t)((r * SAPAD + ccx * 8) * 2), gB + (size_t)r * DK + ccx * 8);
                }
            }
            cp_commit();

            #pragma unroll
            for (int ks = 0; ks < 16; ++ks) {
                const uint32_t kb = (uint32_t)(ks * 32);
                uint32_t a0[4], a1[4], bA[4], bB[4];
                ldsm4(a0, sA + aOff + kb);
                ldsm4(a1, sA + aOff2 + kb);
                ldsm4(bA, sBc + bOff + kb);
                ldsm4(bB, sBc + bOff2 + kb);

                mma16816(acc[0][0], a0, bA[0], bA[2]);
                mma16816(acc[1][0], a1, bA[0], bA[2]);
                mma16816(acc[0][1], a0, bA[1], bA[3]);
                mma16816(acc[1][1], a1, bA[1], bA[3]);
                mma16816(acc[0][2], a0, bB[0], bB[2]);
                mma16816(acc[1][2], a1, bB[0], bB[2]);
                mma16816(acc[0][3], a0, bB[1], bB[3]);
                mma16816(acc[1][3], a1, bB[1], bB[3]);
            }

            const bool offd = (t != band);
            float cc8[8];
            #pragma unroll
            for (int j = 0; j < 8; ++j) cc8[j] = 0.f;

            #pragma unroll
            for (int mf = 0; mf < 2; ++mf)
                #pragma unroll
                for (int nf = 0; nf < 4; ++nf)
                    #pragma unroll
                    for (int q = 0; q < 4; ++q) {
                        float e = fast_ex2(acc[mf][nf][q] * SCALE_L2E);
                        if (!offd) {
                            int rl = wm * 32 + mf * 16 + (q >> 1) * 8 + g;
                            int cl = wn * 32 + nf * 8 + tg * 2 + (q & 1);
                            if (rl == cl) e = 0.f;
                        }
                        racc[mf * 2 + (q >> 1)] += e;
                        cc8[nf * 2 + (q & 1)] += e;
                        acc[mf][nf][q] = 0.f;
                    }

            if (offd) {
                #pragma unroll
                for (int j = 0; j < 8; ++j) {
                    cc8[j] += __shfl_xor_sync(0xffffffffu, cc8[j], 4);
                    cc8[j] += __shfl_xor_sync(0xffffffffu, cc8[j], 8);
                    cc8[j] += __shfl_xor_sync(0xffffffffu, cc8[j], 16);
                }
                if (g == 0) {
                    float* dst = g_cs + (size_t)(band * 4 + wm) * TWO_N
                               + t * NT + wn * 32 + tg * 2;
                    #pragma unroll
                    for (int j = 0; j < 8; ++j) dst[(j >> 1) * 8 + (j & 1)] = cc8[j];
                }
            }

            cp_wait0();
            __syncthreads();
        }

        #pragma unroll
        for (int k2 = 0; k2 < 4; ++k2) {
            racc[k2] += __shfl_xor_sync(0xffffffffu, racc[k2], 1);
            racc[k2] += __shfl_xor_sync(0xffffffffu, racc[k2], 2);
        }
        if (tg == 0) {
            #pragma unroll
            for (int mf = 0; mf < 2; ++mf)
                #pragma unroll
                for (int h = 0; h < 2; ++h)
                    sred[wn * 128 + wm * 32 + mf * 16 + h * 8 + g] = racc[mf * 2 + h];
        }
        __syncthreads();
        if (tid < 128) {
            g_bandparts[(band * NSLOT + slot) * 128 + tid] =
                sred[tid] + sred[128 + tid] + sred[256 + tid] + sred[384 + tid];
        }
        __syncthreads();

        idx += nb;
    }
}

// ---------------- kernel 3: rowsum assembly + log + per-half-band loss partials ----------------
// grid 256 x 512: blockIdx = B*2 + h; block handles rows [h*64, h*64+64) of band B.
// 8-way chunking over prior bands b' < B.
__global__ void rowfinal_kernel() {
    __shared__ float sm[512];
    __shared__ float sl[64];
    __shared__ float sp[64];
    const int B  = blockIdx.x >> 1;
    const int h  = blockIdx.x & 1;
    const int rr = threadIdx.x & 63;       // row within this block's half
    const int chunk = threadIdx.x >> 6;    // 0..7
    const int rl = h * 64 + rr;            // row within band
    const int r  = B * 128 + rl;           // global row/col index
    float sacc = 0.f;
    for (int b = chunk; b < B; b += 8) {
        const float* p4 = g_cs + (size_t)(b * 4) * TWO_N + r;
        sacc += p4[0] + p4[TWO_N] + p4[2 * TWO_N] + p4[3 * TWO_N];
    }
    sm[threadIdx.x] = sacc;
    if (chunk == 1) sp[rr] = (B < 64) ? g_pos[B * 128 + rl] : 0.f;
    __syncthreads();
    if (chunk == 0) {
        float tot = 0.f;
        #pragma unroll
        for (int c = 0; c < 8; ++c) tot += sm[c * 64 + rr];
        const float* bp = g_bandparts + (size_t)B * NSLOT * 128 + rl;
        #pragma unroll
        for (int s = 0; s < NSLOT; ++s) tot += bp[s * 128];
        sl[rr] = logf(tot);
    }
    __syncthreads();
    for (int s = 32; s > 0; s >>= 1) {
        if (threadIdx.x < s) {
            sl[threadIdx.x] += sl[threadIdx.x + s];
            sp[threadIdx.x] += sp[threadIdx.x + s];
        }
        __syncthreads();
    }
    if (threadIdx.x == 0) { g_partA[blockIdx.x] = sl[0]; g_partB[blockIdx.x] = sp[0]; }
}

// ---------------- kernel 4: final reduce over 256 partials ----------------
__global__ void reduce2_kernel(float* __restrict__ out) {
    __shared__ float sa[256], sb[256];
    int tid = threadIdx.x;
    sa[tid] = g_partA[tid]; sb[tid] = g_partB[tid];
    __syncthreads();
    for (int s = 128; s > 0; s >>= 1) {
        if (tid < s) { sa[tid] += sa[tid + s]; sb[tid] += sb[tid + s]; }
        __syncthreads();
    }
    if (tid == 0) out[0] = (sa[0] - 20.0f * sb[0]) / (float)TWO_N;
}

// ---------------- launch ----------------
extern "C" void kernel_launch(void* const* d_in, const int* in_sizes, int n_in,
                              void* d_out, int out_size) {
    const float* z1 = (const float*)d_in[0];
    const float* z2 = (const float*)d_in[1];
    float* out = (float*)d_out;

    normpos_kernel<<<1024, 256>>>(z1, z2);
    zero_bp_kernel<<<96, 256>>>();
    cudaFuncSetAttribute(simloss_sym2, cudaFuncAttributeMaxDynamicSharedMemorySize, SMEM_BYTES);
    simloss_sym2<<<NCTA, 512, SMEM_BYTES>>>();
    rowfinal_kernel<<<256, 512>>>();
    reduce2_kernel<<<1, 256>>>(out);
}